// round 10
// baseline (speedup 1.0000x reference)
#include <cuda_runtime.h>
#include <math.h>

// ---------------------------------------------------------------------------
// GCN(2)->node0->LSTM->FC. Only the 2-hop in-neighborhood of node 0 matters:
// S1 = in-neighbors of 0 (~32), S2 = in-neighbors of S1 (~1100).
// Five kernels:
//   1 init    : incremental reset (1 block), seed node 0, zero barrier
//   2 scan123 : PERSISTENT (592 CTAs = 4/SM resident). Three phases over the
//               SAME per-thread dst indices, separated by relaxed-scope grid
//               barriers (red.release / ld.acquire -- NO __threadfence, so L1
//               is NOT invalidated and phases 2-3 re-read dst from L1):
//                 P1: dst==0            -> e0 list, S1 set, bm1
//                 P2: dst in bm1 (SMEM) -> e1 list, S2 set, bm2
//                 P3: dst in bm2 (SMEM) -> deg atomics
//   3 hlin    : x[:,u]@W1 for u in S2 (16-node stage, high-MLP gather)
//   4 agg     : layer-1 aggregation into acc1 (self loops + e1, atomics)
//   5 tail    : one block: h2 = relu(acc1+b1)@W2 ; node-0 agg ; LSTM ; FC
// ---------------------------------------------------------------------------

#define NN_MAX   100000
#define IND      128
#define H        64
#define S1CAP    512
#define E0CAP    2048
#define ECAP     32768
#define BMW      ((NN_MAX + 31) / 32)   // 3125 words = 12.5 KB
#define PS_B     592                     // 4 CTAs/SM x 148 SMs (resident)
#define PS_T     256
#define PS_N     (PS_B * PS_T)           // 151552 threads
#define HLIN_B   148
#define HN       16                      // nodes staged per hlin block

static __device__ int      g_deg[NN_MAX];
static __device__ int      g_flag1[NN_MAX];   // pos+1 in S1 (0 = not member)
static __device__ int      g_flag2[NN_MAX];   // pos+1 in S2
static __device__ unsigned g_bm1[BMW];
static __device__ unsigned g_bm2[BMW];
static __device__ int      g_s1[S1CAP];
static __device__ int      g_e0[E0CAP];       // src of edges with dst==0
static __device__ int      g_s2[ECAP];
static __device__ int2     g_e1[ECAP];        // edges with dst in S1
static __device__ int      g_cnt1, g_cnt2, g_cntE0, g_cntE1;
static __device__ float    g_hlin[ECAP][H];
static __device__ float    g_acc1[S1CAP][H];
static __device__ float    g_h2[S1CAP][H];
static __device__ unsigned g_barv;            // persistent-kernel barrier

// ---------------------------------------------------------------------------
// Grid barrier WITHOUT a gpu-scope fence: release-RED arrival + acquire-LD
// spin. Orders all prior memory ops (release) without emitting CCTL.IVALL,
// so this SM's L1D lines (read-only dst) survive the phase boundary.
__device__ __forceinline__ void pbar(unsigned target) {
    __syncthreads();
    if (threadIdx.x == 0) {
        asm volatile("red.release.gpu.global.add.u32 [%0], 1;"
                     :: "l"(&g_barv) : "memory");
        unsigned r;
        do {
            asm volatile("ld.acquire.gpu.global.u32 %0, [%1];"
                         : "=r"(r) : "l"(&g_barv) : "memory");
        } while (r < target);
    }
    __syncthreads();
}

// ---------------------------------------------------------------------------
// Incremental init: reset exactly the entries the previous run touched,
// then seed node 0. First call sees counters==0 (static zero-init) -> no-op
// loops, seed only. Always leaves the identical canonical state.
__global__ void k_init(void) {
    int tid = threadIdx.x;
    int m1 = g_cnt1; if (m1 > S1CAP) m1 = S1CAP;
    int m2 = g_cnt2; if (m2 > ECAP)  m2 = ECAP;
    for (int j = 1 + tid; j < m1; j += 512) {
        int u = g_s1[j];
        g_flag1[u] = 0;
        atomicAnd(&g_bm1[u >> 5], ~(1u << (u & 31)));
    }
    for (int j = 1 + tid; j < m2; j += 512) {
        int u = g_s2[j];
        g_flag2[u] = 0;
        g_deg[u]   = 0;
        atomicAnd(&g_bm2[u >> 5], ~(1u << (u & 31)));
    }
    for (int k = tid; k < m1 * H; k += 512) ((float*)g_acc1)[k] = 0.0f;
    __syncthreads();
    if (tid == 0) {
        g_cnt1 = 1; g_cnt2 = 1; g_cntE0 = 0; g_cntE1 = 0;
        g_s1[0] = 0; g_s2[0] = 0;
        g_flag1[0] = 1; g_flag2[0] = 1;
        g_deg[0] = 0;
        g_barv = 0;
        atomicOr(&g_bm1[0], 1u);
        atomicOr(&g_bm2[0], 1u);
    }
}

// ---------------------------------------------------------------------------
__device__ __forceinline__ void s1_one(const int* __restrict__ src, int d, int idx) {
    if (d == 0) {
        int s = __ldcg(&src[idx]);
        int p = atomicAdd(&g_cntE0, 1);
        if (p < E0CAP) g_e0[p] = s;
        if (atomicCAS(&g_flag1[s], 0, -1) == 0) {
            int q = atomicAdd(&g_cnt1, 1);
            if (q < S1CAP) g_s1[q] = s;
            g_flag1[s] = q + 1;
            atomicOr(&g_bm1[s >> 5], 1u << (s & 31));
            if (atomicCAS(&g_flag2[s], 0, -1) == 0) {
                int r = atomicAdd(&g_cnt2, 1);
                if (r < ECAP) g_s2[r] = s;
                g_flag2[s] = r + 1;
                atomicOr(&g_bm2[s >> 5], 1u << (s & 31));
            }
        }
    }
}

__device__ __forceinline__ void s2_one(const unsigned* sbm,
                                       const int* __restrict__ src, int d, int idx) {
    if ((sbm[d >> 5] >> (d & 31)) & 1u) {
        int s = __ldcg(&src[idx]);
        int p = atomicAdd(&g_cntE1, 1);
        if (p < ECAP) g_e1[p] = make_int2(s, d);
        if (atomicCAS(&g_flag2[s], 0, -1) == 0) {
            int r = atomicAdd(&g_cnt2, 1);
            if (r < ECAP) g_s2[r] = s;
            g_flag2[s] = r + 1;
            atomicOr(&g_bm2[s >> 5], 1u << (s & 31));
        }
    }
}

// ---------------------------------------------------------------------------
// Persistent 3-phase scan. Same thread->index mapping in every phase, so
// phases 2-3 hit L1 on dst (loaded with __ldg = L1-caching).
__global__ void __launch_bounds__(PS_T, 4)
k_scan123(const int* __restrict__ src, const int* __restrict__ dst, int E) {
    __shared__ unsigned sbm[BMW];   // 12.5 KB; bm1 in P2, bm2 in P3
    int gid = blockIdx.x * PS_T + threadIdx.x;
    int E4 = E >> 2;
    const int4* d4 = (const int4*)dst;

    // ---------------- P1: dst==0 ----------------
    {
        int i = gid;
        for (; i + 3 * PS_N < E4; i += 4 * PS_N) {
            int4 v0 = __ldg(&d4[i]);
            int4 v1 = __ldg(&d4[i + PS_N]);
            int4 v2 = __ldg(&d4[i + 2 * PS_N]);
            int4 v3 = __ldg(&d4[i + 3 * PS_N]);
            int j;
            j = i;            s1_one(src, v0.x, 4*j); s1_one(src, v0.y, 4*j+1); s1_one(src, v0.z, 4*j+2); s1_one(src, v0.w, 4*j+3);
            j = i + PS_N;     s1_one(src, v1.x, 4*j); s1_one(src, v1.y, 4*j+1); s1_one(src, v1.z, 4*j+2); s1_one(src, v1.w, 4*j+3);
            j = i + 2 * PS_N; s1_one(src, v2.x, 4*j); s1_one(src, v2.y, 4*j+1); s1_one(src, v2.z, 4*j+2); s1_one(src, v2.w, 4*j+3);
            j = i + 3 * PS_N; s1_one(src, v3.x, 4*j); s1_one(src, v3.y, 4*j+1); s1_one(src, v3.z, 4*j+2); s1_one(src, v3.w, 4*j+3);
        }
        for (; i < E4; i += PS_N) {
            int4 v = __ldg(&d4[i]);
            s1_one(src, v.x, 4*i); s1_one(src, v.y, 4*i+1); s1_one(src, v.z, 4*i+2); s1_one(src, v.w, 4*i+3);
        }
        for (int j = (E4 << 2) + gid; j < E; j += PS_N) s1_one(src, __ldg(&dst[j]), j);
    }
    pbar(PS_B);

    // ---------------- P2: dst in bm1 ----------------
    for (int k = threadIdx.x; k < BMW; k += PS_T) sbm[k] = __ldcg(&g_bm1[k]);
    __syncthreads();
    {
        int i = gid;
        for (; i + 3 * PS_N < E4; i += 4 * PS_N) {
            int4 v0 = __ldg(&d4[i]);
            int4 v1 = __ldg(&d4[i + PS_N]);
            int4 v2 = __ldg(&d4[i + 2 * PS_N]);
            int4 v3 = __ldg(&d4[i + 3 * PS_N]);
            int j;
            j = i;            s2_one(sbm, src, v0.x, 4*j); s2_one(sbm, src, v0.y, 4*j+1); s2_one(sbm, src, v0.z, 4*j+2); s2_one(sbm, src, v0.w, 4*j+3);
            j = i + PS_N;     s2_one(sbm, src, v1.x, 4*j); s2_one(sbm, src, v1.y, 4*j+1); s2_one(sbm, src, v1.z, 4*j+2); s2_one(sbm, src, v1.w, 4*j+3);
            j = i + 2 * PS_N; s2_one(sbm, src, v2.x, 4*j); s2_one(sbm, src, v2.y, 4*j+1); s2_one(sbm, src, v2.z, 4*j+2); s2_one(sbm, src, v2.w, 4*j+3);
            j = i + 3 * PS_N; s2_one(sbm, src, v3.x, 4*j); s2_one(sbm, src, v3.y, 4*j+1); s2_one(sbm, src, v3.z, 4*j+2); s2_one(sbm, src, v3.w, 4*j+3);
        }
        for (; i < E4; i += PS_N) {
            int4 v = __ldg(&d4[i]);
            s2_one(sbm, src, v.x, 4*i); s2_one(sbm, src, v.y, 4*i+1); s2_one(sbm, src, v.z, 4*i+2); s2_one(sbm, src, v.w, 4*i+3);
        }
        for (int j = (E4 << 2) + gid; j < E; j += PS_N) {
            int d = __ldg(&dst[j]);
            s2_one(sbm, src, d, j);
        }
    }
    pbar(2 * PS_B);

    // ---------------- P3: dst in bm2 -> deg ----------------
    for (int k = threadIdx.x; k < BMW; k += PS_T) sbm[k] = __ldcg(&g_bm2[k]);
    __syncthreads();
    #define S3(dd) if ((sbm[(dd) >> 5] >> ((dd) & 31)) & 1u) atomicAdd(&g_deg[dd], 1)
    {
        int i = gid;
        for (; i + 3 * PS_N < E4; i += 4 * PS_N) {
            int4 v0 = __ldg(&d4[i]);
            int4 v1 = __ldg(&d4[i + PS_N]);
            int4 v2 = __ldg(&d4[i + 2 * PS_N]);
            int4 v3 = __ldg(&d4[i + 3 * PS_N]);
            S3(v0.x); S3(v0.y); S3(v0.z); S3(v0.w);
            S3(v1.x); S3(v1.y); S3(v1.z); S3(v1.w);
            S3(v2.x); S3(v2.y); S3(v2.z); S3(v2.w);
            S3(v3.x); S3(v3.y); S3(v3.z); S3(v3.w);
        }
        for (; i < E4; i += PS_N) {
            int4 v = __ldg(&d4[i]);
            S3(v.x); S3(v.y); S3(v.z); S3(v.w);
        }
        for (int j = (E4 << 2) + gid; j < E; j += PS_N) { int dd = __ldg(&dst[j]); S3(dd); }
    }
    #undef S3
}

// ---------------------------------------------------------------------------
// hlin = x[:,u] @ W1 for u in S2. 16 nodes staged per block -> 8 scattered
// loads in flight per thread, one sync, then 4 dot-outputs per thread.
__global__ void __launch_bounds__(PS_T)
k_hlin(const float* __restrict__ x, const float* __restrict__ W1, int N) {
    __shared__ float sW1[IND * H];    // 32 KB
    __shared__ float sx[HN][IND];     // 8 KB
    int tid = threadIdx.x;
    for (int k = tid; k < IND * H; k += PS_T) sW1[k] = W1[k];
    int m2 = g_cnt2; if (m2 > ECAP) m2 = ECAP;
    for (int base = blockIdx.x * HN; base < m2; base += HLIN_B * HN) {
        for (int k = tid; k < HN * IND; k += PS_T) {
            int node = k >> 7;
            int d    = k & 127;
            int j    = base + node;
            if (j < m2) sx[node][d] = __ldg(&x[(size_t)d * N + g_s2[j]]);
        }
        __syncthreads();
        for (int k = tid; k < HN * H; k += PS_T) {
            int node = k >> 6;
            int o    = k & 63;
            int j    = base + node;
            if (j < m2) {
                float acc = 0.0f;
                #pragma unroll
                for (int d = 0; d < IND; d++) acc += sx[node][d] * sW1[d * H + o];
                g_hlin[j][o] = acc;
            }
        }
        __syncthreads();
    }
}

// ---------------------------------------------------------------------------
// Layer-1 aggregation: self loops for S1 nodes + e1 edge scatter.
__global__ void k_agg(void) {
    int sub = threadIdx.x >> 6;          // 4 groups of 64 per block
    int tt  = threadIdx.x & 63;
    int ng  = gridDim.x * 4;
    int gi  = blockIdx.x * 4 + sub;
    int m1 = g_cnt1; if (m1 > S1CAP) m1 = S1CAP;
    for (int j = gi; j < m1; j += ng) {
        int u  = g_s1[j];
        float di = rsqrtf((float)g_deg[u] + 1.0f);
        int p2 = g_flag2[u] - 1;
        atomicAdd(&g_acc1[j][tt], di * di * g_hlin[p2][tt]);
    }
    int mE = g_cntE1; if (mE > ECAP) mE = ECAP;
    for (int e = gi; e < mE; e += ng) {
        int2 ed = g_e1[e];
        int dp = g_flag1[ed.y] - 1;
        int sp = g_flag2[ed.x] - 1;
        float nrm = rsqrtf((float)g_deg[ed.x] + 1.0f) * rsqrtf((float)g_deg[ed.y] + 1.0f);
        atomicAdd(&g_acc1[dp][tt], nrm * g_hlin[sp][tt]);
    }
}

// ---------------------------------------------------------------------------
// Single block: h2 for all S1 nodes, node-0 layer-2 aggregation, LSTM, FC.
__global__ void __launch_bounds__(512)
k_tail(const float* __restrict__ b1, const float* __restrict__ W2,
       const float* __restrict__ b2, const float* __restrict__ w_ih,
       const float* __restrict__ b_ih, const float* __restrict__ b_hh,
       const float* __restrict__ fc_w, const float* __restrict__ fc_b,
       float* __restrict__ out) {
    __shared__ float sW2[H * H];        // 16 KB
    __shared__ float h1buf[8][H];       // 2 KB
    __shared__ float z[H], gates[4 * H], red[H];
    __shared__ float scof[256];
    __shared__ int   sspb[256];

    int tid = threadIdx.x;
    for (int k = tid; k < H * H; k += 512) sW2[k] = W2[k];
    __syncthreads();

    int m1 = g_cnt1; if (m1 > S1CAP) m1 = S1CAP;
    int sub = tid >> 6, tt = tid & 63;
    for (int j0 = 0; j0 < m1; j0 += 8) {
        int j = j0 + sub;
        if (j < m1) h1buf[sub][tt] = fmaxf(g_acc1[j][tt] + b1[tt], 0.0f);
        __syncthreads();
        if (j < m1) {
            float acc = 0.0f;
            #pragma unroll
            for (int h = 0; h < H; h++) acc += h1buf[sub][h] * sW2[h * H + tt];
            g_h2[j][tt] = acc;
        }
        __syncthreads();
    }

    // node-0 layer-2 aggregation
    int m0 = g_cntE0; if (m0 > E0CAP) m0 = E0CAP;
    float d0 = rsqrtf((float)g_deg[0] + 1.0f);
    float zv = 0.0f;
    if (tid < H) zv = b2[tid] + d0 * d0 * g_h2[0][tid];
    for (int base = 0; base < m0; base += 256) {
        int k = base + tid;
        if (tid < 256 && k < m0) {
            int s = g_e0[k];
            scof[tid] = rsqrtf((float)g_deg[s] + 1.0f) * d0;
            sspb[tid] = g_flag1[s] - 1;
        }
        __syncthreads();
        int lim = m0 - base; if (lim > 256) lim = 256;
        if (tid < H)
            for (int e = 0; e < lim; e++) zv += scof[e] * g_h2[sspb[e]][tid];
        __syncthreads();
    }
    if (tid < H) z[tid] = zv;
    __syncthreads();

    if (tid < 4 * H) {
        float a = b_ih[tid] + b_hh[tid];
        #pragma unroll
        for (int h = 0; h < H; h++) a += __ldg(&w_ih[tid * H + h]) * z[h];
        gates[tid] = a;
    }
    __syncthreads();
    if (tid < H) {
        float ig = gates[tid];
        float gg = gates[2 * H + tid];
        float og = gates[3 * H + tid];
        float si = 1.0f / (1.0f + expf(-ig));
        float c  = si * tanhf(gg);
        float so = 1.0f / (1.0f + expf(-og));
        float hy = so * tanhf(c);
        red[tid] = hy * fc_w[tid];
    }
    __syncthreads();
    if (tid == 0) {
        float s = 0.0f;
        for (int k = 0; k < H; k++) s += red[k];
        out[0] = s + fc_b[0];
    }
}

// ---------------------------------------------------------------------------
extern "C" void kernel_launch(void* const* d_in, const int* in_sizes, int n_in,
                              void* d_out, int out_size) {
    const float* x    = (const float*)d_in[0];
    const int*   ei   = (const int*)d_in[1];
    const float* W1   = (const float*)d_in[2];
    const float* b1   = (const float*)d_in[3];
    const float* W2   = (const float*)d_in[4];
    const float* b2   = (const float*)d_in[5];
    const float* w_ih = (const float*)d_in[6];
    // d_in[7] = w_hh (unused: h0 = c0 = 0)
    const float* b_ih = (const float*)d_in[8];
    const float* b_hh = (const float*)d_in[9];
    const float* fc_w = (const float*)d_in[10];
    const float* fc_b = (const float*)d_in[11];
    float* out = (float*)d_out;

    int N = in_sizes[0] / IND;
    int E = in_sizes[1] / 2;
    const int* src = ei;
    const int* dst = ei + E;

    k_init<<<1, 512>>>();
    k_scan123<<<PS_B, PS_T>>>(src, dst, E);
    k_hlin<<<HLIN_B, PS_T>>>(x, W1, N);
    k_agg<<<148, 256>>>();
    k_tail<<<1, 512>>>(b1, W2, b2, w_ih, b_ih, b_hh, fc_w, fc_b, out);
}

// round 11
// speedup vs baseline: 1.5169x; 1.5169x over previous
#include <cuda_runtime.h>
#include <math.h>

// ---------------------------------------------------------------------------
// GCN(2)->node0->LSTM->FC. Only the 2-hop in-neighborhood of node 0 matters:
// S1 = in-neighbors of 0 (~32), S2 = in-neighbors of S1 (~1100).
// Seven kernels, each in its fastest measured standalone form:
//   1 init  : incremental reset of prev-run entries (1 block), seed node 0
//   2 scan1 : dst==0            -> e0 list, S1 set, bm1     (ALU test only)
//   3 scan2 : dst in bm1 (SMEM) -> e1 list, S2 set, bm2     (LDS-bound)
//   4 scan3 : dst in bm2 (SMEM) -> deg atomics              (LDS-bound)
//   5 hlin  : x[:,u]@W1 for u in S2 (16-node stage, high-MLP gather)
//   6 agg   : layer-1 aggregation, ONE dependent-chain iteration per group
//   7 tail  : one block: h2 = relu(acc1+b1)@W2 ; node-0 agg ; LSTM ; FC
// LDS-bound stages are never co-located (they serialize on the crossbar).
// ---------------------------------------------------------------------------

#define NN_MAX   100000
#define IND      128
#define H        64
#define S1CAP    512
#define E0CAP    2048
#define ECAP     32768
#define BMW      ((NN_MAX + 31) / 32)   // 3125 words = 12.5 KB
#define SCAN_B   296
#define SCAN_T   512
#define HLIN_B   148
#define HN       16                      // nodes staged per hlin block

static __device__ int      g_deg[NN_MAX];
static __device__ int      g_flag1[NN_MAX];   // pos+1 in S1 (0 = not member)
static __device__ int      g_flag2[NN_MAX];   // pos+1 in S2
static __device__ unsigned g_bm1[BMW];
static __device__ unsigned g_bm2[BMW];
static __device__ int      g_s1[S1CAP];
static __device__ int      g_e0[E0CAP];       // src of edges with dst==0
static __device__ int      g_s2[ECAP];
static __device__ int2     g_e1[ECAP];        // edges with dst in S1
static __device__ int      g_cnt1, g_cnt2, g_cntE0, g_cntE1;
static __device__ float    g_hlin[ECAP][H];
static __device__ float    g_acc1[S1CAP][H];
static __device__ float    g_h2[S1CAP][H];

// ---------------------------------------------------------------------------
// Incremental init: reset exactly the entries the previous run touched,
// then seed node 0. First call sees counters==0 (static zero-init) -> no-op
// loops, seed only. Always leaves the identical canonical state.
__global__ void k_init(void) {
    int tid = threadIdx.x;
    int m1 = g_cnt1; if (m1 > S1CAP) m1 = S1CAP;
    int m2 = g_cnt2; if (m2 > ECAP)  m2 = ECAP;
    for (int j = 1 + tid; j < m1; j += 512) {
        int u = g_s1[j];
        g_flag1[u] = 0;
        atomicAnd(&g_bm1[u >> 5], ~(1u << (u & 31)));
    }
    for (int j = 1 + tid; j < m2; j += 512) {
        int u = g_s2[j];
        g_flag2[u] = 0;
        g_deg[u]   = 0;
        atomicAnd(&g_bm2[u >> 5], ~(1u << (u & 31)));
    }
    for (int k = tid; k < m1 * H; k += 512) ((float*)g_acc1)[k] = 0.0f;
    __syncthreads();
    if (tid == 0) {
        g_cnt1 = 1; g_cnt2 = 1; g_cntE0 = 0; g_cntE1 = 0;
        g_s1[0] = 0; g_s2[0] = 0;
        g_flag1[0] = 1; g_flag2[0] = 1;
        g_deg[0] = 0;
        atomicOr(&g_bm1[0], 1u);
        atomicOr(&g_bm2[0], 1u);
    }
}

// ---------------------------------------------------------------------------
__device__ __forceinline__ void s1_one(const int* __restrict__ src, int d, int idx) {
    if (d == 0) {
        int s = __ldcg(&src[idx]);
        int p = atomicAdd(&g_cntE0, 1);
        if (p < E0CAP) g_e0[p] = s;
        if (atomicCAS(&g_flag1[s], 0, -1) == 0) {
            int q = atomicAdd(&g_cnt1, 1);
            if (q < S1CAP) g_s1[q] = s;
            g_flag1[s] = q + 1;
            atomicOr(&g_bm1[s >> 5], 1u << (s & 31));
            if (atomicCAS(&g_flag2[s], 0, -1) == 0) {
                int r = atomicAdd(&g_cnt2, 1);
                if (r < ECAP) g_s2[r] = s;
                g_flag2[s] = r + 1;
                atomicOr(&g_bm2[s >> 5], 1u << (s & 31));
            }
        }
    }
}

__global__ void __launch_bounds__(SCAN_T)
k_scan1(const int* __restrict__ src, const int* __restrict__ dst, int E) {
    int gid = blockIdx.x * SCAN_T + threadIdx.x;
    int nth = SCAN_B * SCAN_T;
    int E4 = E >> 2;
    const int4* d4 = (const int4*)dst;
    int i = gid;
    for (; i + 3 * nth < E4; i += 4 * nth) {
        int4 v0 = __ldcg(&d4[i]);
        int4 v1 = __ldcg(&d4[i + nth]);
        int4 v2 = __ldcg(&d4[i + 2 * nth]);
        int4 v3 = __ldcg(&d4[i + 3 * nth]);
        int j;
        j = i;           s1_one(src, v0.x, 4*j); s1_one(src, v0.y, 4*j+1); s1_one(src, v0.z, 4*j+2); s1_one(src, v0.w, 4*j+3);
        j = i + nth;     s1_one(src, v1.x, 4*j); s1_one(src, v1.y, 4*j+1); s1_one(src, v1.z, 4*j+2); s1_one(src, v1.w, 4*j+3);
        j = i + 2 * nth; s1_one(src, v2.x, 4*j); s1_one(src, v2.y, 4*j+1); s1_one(src, v2.z, 4*j+2); s1_one(src, v2.w, 4*j+3);
        j = i + 3 * nth; s1_one(src, v3.x, 4*j); s1_one(src, v3.y, 4*j+1); s1_one(src, v3.z, 4*j+2); s1_one(src, v3.w, 4*j+3);
    }
    for (; i < E4; i += nth) {
        int4 v = __ldcg(&d4[i]);
        s1_one(src, v.x, 4*i); s1_one(src, v.y, 4*i+1); s1_one(src, v.z, 4*i+2); s1_one(src, v.w, 4*i+3);
    }
    for (int j = (E4 << 2) + gid; j < E; j += nth) s1_one(src, __ldcg(&dst[j]), j);
}

// ---------------------------------------------------------------------------
__device__ __forceinline__ void s2_one(const unsigned* sbm,
                                       const int* __restrict__ src, int d, int idx) {
    if ((sbm[d >> 5] >> (d & 31)) & 1u) {
        int s = __ldcg(&src[idx]);
        int p = atomicAdd(&g_cntE1, 1);
        if (p < ECAP) g_e1[p] = make_int2(s, d);
        if (atomicCAS(&g_flag2[s], 0, -1) == 0) {
            int r = atomicAdd(&g_cnt2, 1);
            if (r < ECAP) g_s2[r] = s;
            g_flag2[s] = r + 1;
            atomicOr(&g_bm2[s >> 5], 1u << (s & 31));
        }
    }
}

__global__ void __launch_bounds__(SCAN_T)
k_scan2(const int* __restrict__ src, const int* __restrict__ dst, int E) {
    __shared__ unsigned sbm[BMW];
    for (int k = threadIdx.x; k < BMW; k += SCAN_T) sbm[k] = __ldg(&g_bm1[k]);
    __syncthreads();
    int gid = blockIdx.x * SCAN_T + threadIdx.x;
    int nth = SCAN_B * SCAN_T;
    int E4 = E >> 2;
    const int4* d4 = (const int4*)dst;
    int i = gid;
    for (; i + 3 * nth < E4; i += 4 * nth) {
        int4 v0 = __ldcg(&d4[i]);
        int4 v1 = __ldcg(&d4[i + nth]);
        int4 v2 = __ldcg(&d4[i + 2 * nth]);
        int4 v3 = __ldcg(&d4[i + 3 * nth]);
        int j;
        j = i;           s2_one(sbm, src, v0.x, 4*j); s2_one(sbm, src, v0.y, 4*j+1); s2_one(sbm, src, v0.z, 4*j+2); s2_one(sbm, src, v0.w, 4*j+3);
        j = i + nth;     s2_one(sbm, src, v1.x, 4*j); s2_one(sbm, src, v1.y, 4*j+1); s2_one(sbm, src, v1.z, 4*j+2); s2_one(sbm, src, v1.w, 4*j+3);
        j = i + 2 * nth; s2_one(sbm, src, v2.x, 4*j); s2_one(sbm, src, v2.y, 4*j+1); s2_one(sbm, src, v2.z, 4*j+2); s2_one(sbm, src, v2.w, 4*j+3);
        j = i + 3 * nth; s2_one(sbm, src, v3.x, 4*j); s2_one(sbm, src, v3.y, 4*j+1); s2_one(sbm, src, v3.z, 4*j+2); s2_one(sbm, src, v3.w, 4*j+3);
    }
    for (; i < E4; i += nth) {
        int4 v = __ldcg(&d4[i]);
        s2_one(sbm, src, v.x, 4*i); s2_one(sbm, src, v.y, 4*i+1); s2_one(sbm, src, v.z, 4*i+2); s2_one(sbm, src, v.w, 4*i+3);
    }
    for (int j = (E4 << 2) + gid; j < E; j += nth) {
        int d = __ldcg(&dst[j]);
        s2_one(sbm, src, d, j);
    }
}

// ---------------------------------------------------------------------------
// Degree scan, bm2-gated (standalone; LDS-bound, gets all SMs to itself).
__global__ void __launch_bounds__(SCAN_T)
k_scan3(const int* __restrict__ dst, int E) {
    __shared__ unsigned sbm[BMW];
    for (int k = threadIdx.x; k < BMW; k += SCAN_T) sbm[k] = __ldg(&g_bm2[k]);
    __syncthreads();
    int gid = blockIdx.x * SCAN_T + threadIdx.x;
    int nth = SCAN_B * SCAN_T;
    int E4 = E >> 2;
    const int4* d4 = (const int4*)dst;
    #define S3(dd) if ((sbm[(dd) >> 5] >> ((dd) & 31)) & 1u) atomicAdd(&g_deg[dd], 1)
    int i = gid;
    for (; i + 3 * nth < E4; i += 4 * nth) {
        int4 v0 = __ldcg(&d4[i]);
        int4 v1 = __ldcg(&d4[i + nth]);
        int4 v2 = __ldcg(&d4[i + 2 * nth]);
        int4 v3 = __ldcg(&d4[i + 3 * nth]);
        S3(v0.x); S3(v0.y); S3(v0.z); S3(v0.w);
        S3(v1.x); S3(v1.y); S3(v1.z); S3(v1.w);
        S3(v2.x); S3(v2.y); S3(v2.z); S3(v2.w);
        S3(v3.x); S3(v3.y); S3(v3.z); S3(v3.w);
    }
    for (; i < E4; i += nth) {
        int4 v = __ldcg(&d4[i]);
        S3(v.x); S3(v.y); S3(v.z); S3(v.w);
    }
    for (int j = (E4 << 2) + gid; j < E; j += nth) { int dd = __ldcg(&dst[j]); S3(dd); }
    #undef S3
}

// ---------------------------------------------------------------------------
// hlin = x[:,u] @ W1 for u in S2. 16 nodes staged per block -> 8 scattered
// loads in flight per thread, one sync, then 4 dot-outputs per thread.
// For m2 ~1100: 148 blocks x 16 nodes = 2368 >= m2 -> a single stage.
__global__ void __launch_bounds__(SCAN_T)
k_hlin(const float* __restrict__ x, const float* __restrict__ W1, int N) {
    __shared__ float sW1[IND * H];    // 32 KB
    __shared__ float sx[HN][IND];     // 8 KB
    int tid = threadIdx.x;
    for (int k = tid; k < IND * H; k += SCAN_T) sW1[k] = W1[k];
    int m2 = g_cnt2; if (m2 > ECAP) m2 = ECAP;
    for (int base = blockIdx.x * HN; base < m2; base += HLIN_B * HN) {
        for (int k = tid; k < HN * IND; k += SCAN_T) {
            int node = k >> 7;
            int d    = k & 127;
            int j    = base + node;
            if (j < m2) sx[node][d] = __ldg(&x[(size_t)d * N + g_s2[j]]);
        }
        __syncthreads();
        for (int k = tid; k < HN * H; k += SCAN_T) {
            int node = k >> 6;
            int o    = k & 63;
            int j    = base + node;
            if (j < m2) {
                float acc = 0.0f;
                #pragma unroll
                for (int d = 0; d < IND; d++) acc += sx[node][d] * sW1[d * H + o];
                g_hlin[j][o] = acc;
            }
        }
        __syncthreads();
    }
}

// ---------------------------------------------------------------------------
// Layer-1 aggregation, latency-optimized: self loops and edges share ONE
// index space over 1184 groups of 64 threads -> a single dependent-chain
// iteration per group, metadata loads issued concurrently via __ldg.
__global__ void __launch_bounds__(256)
k_agg(void) {
    int tt      = threadIdx.x & 63;
    int group   = blockIdx.x * 4 + (threadIdx.x >> 6);
    int ngroups = gridDim.x * 4;
    int m1 = g_cnt1; if (m1 > S1CAP) m1 = S1CAP;
    int mE = g_cntE1; if (mE > ECAP) mE = ECAP;
    int total = m1 + mE;
    for (int t = group; t < total; t += ngroups) {
        if (t < m1) {
            int u  = __ldg(&g_s1[t]);
            float di = rsqrtf((float)__ldg(&g_deg[u]) + 1.0f);
            int p2 = __ldg(&g_flag2[u]) - 1;
            atomicAdd(&g_acc1[t][tt], di * di * __ldg(&g_hlin[p2][tt]));
        } else {
            int e = t - m1;
            int2 ed = __ldg(&g_e1[e]);
            int dp = __ldg(&g_flag1[ed.y]) - 1;
            int sp = __ldg(&g_flag2[ed.x]) - 1;
            float nrm = rsqrtf((float)__ldg(&g_deg[ed.x]) + 1.0f)
                      * rsqrtf((float)__ldg(&g_deg[ed.y]) + 1.0f);
            atomicAdd(&g_acc1[dp][tt], nrm * __ldg(&g_hlin[sp][tt]));
        }
    }
}

// ---------------------------------------------------------------------------
// Single block: h2 for all S1 nodes, node-0 layer-2 aggregation, LSTM, FC.
__global__ void __launch_bounds__(512)
k_tail(const float* __restrict__ b1, const float* __restrict__ W2,
       const float* __restrict__ b2, const float* __restrict__ w_ih,
       const float* __restrict__ b_ih, const float* __restrict__ b_hh,
       const float* __restrict__ fc_w, const float* __restrict__ fc_b,
       float* __restrict__ out) {
    __shared__ float sW2[H * H];        // 16 KB
    __shared__ float h1buf[8][H];       // 2 KB
    __shared__ float z[H], gates[4 * H], red[H];
    __shared__ float scof[256];
    __shared__ int   sspb[256];

    int tid = threadIdx.x;
    for (int k = tid; k < H * H; k += 512) sW2[k] = W2[k];
    __syncthreads();

    int m1 = g_cnt1; if (m1 > S1CAP) m1 = S1CAP;
    int sub = tid >> 6, tt = tid & 63;
    for (int j0 = 0; j0 < m1; j0 += 8) {
        int j = j0 + sub;
        if (j < m1) h1buf[sub][tt] = fmaxf(g_acc1[j][tt] + b1[tt], 0.0f);
        __syncthreads();
        if (j < m1) {
            float acc = 0.0f;
            #pragma unroll
            for (int h = 0; h < H; h++) acc += h1buf[sub][h] * sW2[h * H + tt];
            g_h2[j][tt] = acc;
        }
        __syncthreads();
    }

    // node-0 layer-2 aggregation
    int m0 = g_cntE0; if (m0 > E0CAP) m0 = E0CAP;
    float d0 = rsqrtf((float)g_deg[0] + 1.0f);
    float zv = 0.0f;
    if (tid < H) zv = b2[tid] + d0 * d0 * g_h2[0][tid];
    for (int base = 0; base < m0; base += 256) {
        int k = base + tid;
        if (tid < 256 && k < m0) {
            int s = g_e0[k];
            scof[tid] = rsqrtf((float)g_deg[s] + 1.0f) * d0;
            sspb[tid] = g_flag1[s] - 1;
        }
        __syncthreads();
        int lim = m0 - base; if (lim > 256) lim = 256;
        if (tid < H)
            for (int e = 0; e < lim; e++) zv += scof[e] * g_h2[sspb[e]][tid];
        __syncthreads();
    }
    if (tid < H) z[tid] = zv;
    __syncthreads();

    if (tid < 4 * H) {
        float a = b_ih[tid] + b_hh[tid];
        #pragma unroll
        for (int h = 0; h < H; h++) a += __ldg(&w_ih[tid * H + h]) * z[h];
        gates[tid] = a;
    }
    __syncthreads();
    if (tid < H) {
        float ig = gates[tid];
        float gg = gates[2 * H + tid];
        float og = gates[3 * H + tid];
        float si = 1.0f / (1.0f + expf(-ig));
        float c  = si * tanhf(gg);
        float so = 1.0f / (1.0f + expf(-og));
        float hy = so * tanhf(c);
        red[tid] = hy * fc_w[tid];
    }
    __syncthreads();
    if (tid == 0) {
        float s = 0.0f;
        for (int k = 0; k < H; k++) s += red[k];
        out[0] = s + fc_b[0];
    }
}

// ---------------------------------------------------------------------------
extern "C" void kernel_launch(void* const* d_in, const int* in_sizes, int n_in,
                              void* d_out, int out_size) {
    const float* x    = (const float*)d_in[0];
    const int*   ei   = (const int*)d_in[1];
    const float* W1   = (const float*)d_in[2];
    const float* b1   = (const float*)d_in[3];
    const float* W2   = (const float*)d_in[4];
    const float* b2   = (const float*)d_in[5];
    const float* w_ih = (const float*)d_in[6];
    // d_in[7] = w_hh (unused: h0 = c0 = 0)
    const float* b_ih = (const float*)d_in[8];
    const float* b_hh = (const float*)d_in[9];
    const float* fc_w = (const float*)d_in[10];
    const float* fc_b = (const float*)d_in[11];
    float* out = (float*)d_out;

    int N = in_sizes[0] / IND;
    int E = in_sizes[1] / 2;
    const int* src = ei;
    const int* dst = ei + E;

    k_init<<<1, 512>>>();
    k_scan1<<<SCAN_B, SCAN_T>>>(src, dst, E);
    k_scan2<<<SCAN_B, SCAN_T>>>(src, dst, E);
    k_scan3<<<SCAN_B, SCAN_T>>>(dst, E);
    k_hlin<<<HLIN_B, SCAN_T>>>(x, W1, N);
    k_agg<<<SCAN_B, 256>>>();
    k_tail<<<1, 512>>>(b1, W2, b2, w_ih, b_ih, b_hh, fc_w, fc_b, out);
}

// round 12
// speedup vs baseline: 1.5186x; 1.0011x over previous
#include <cuda_runtime.h>
#include <math.h>

// ---------------------------------------------------------------------------
// GCN(2)->node0->LSTM->FC. Only the 2-hop in-neighborhood of node 0 matters:
// S1 = in-neighbors of 0 (~32), S2 = in-neighbors of S1 (~1100).
// SIX kernels (no init kernel: canonical state comes from static device
// initializers on the first run and from k_tail's epilogue afterwards):
//   1 scan1 : dst==0 via umin-reduction  -> e0 list, S1 set, bm1
//   2 scan2 : dst in bm1 (SMEM, OR-combined funnel probes) -> e1, S2, bm2
//   3 scan3 : dst in bm2 (SMEM, OR-combined funnel probes) -> deg atomics
//   4 hlin  : x[:,u]@W1 for u in S2 (16-node stage, high-MLP gather)
//   5 agg   : layer-1 aggregation, one dependent-chain iteration per group
//   6 tail  : h2 = relu(acc1+b1)@W2 ; node-0 agg ; LSTM ; FC ; then RESET
//             all touched state back to canonical (epilogue, single block)
// Scans: 4 CTAs/SM x 384 thr (75% occ), whole per-thread workload issued as
// one predicated 4x int4 batch (max MLP), sentinel index -> zero bitmap word.
// ---------------------------------------------------------------------------

#define NN_MAX   100000
#define SENT     100000                  // sentinel node id: probes zero word
#define IND      128
#define H        64
#define S1CAP    512
#define E0CAP    2048
#define ECAP     32768
#define BMW      ((NN_MAX + 31) / 32)   // 3125 words; +1 sentinel word
#define SCAN_B   592
#define SCAN_T   384
#define NTH      (SCAN_B * SCAN_T)
#define HLIN_B   148
#define HLIN_T   512
#define HN       16

static __device__ int      g_deg[NN_MAX];
static __device__ int      g_flag1[NN_MAX] = {1};   // node 0 seeded: pos+1
static __device__ int      g_flag2[NN_MAX] = {1};
static __device__ unsigned g_bm1[BMW + 1] = {1u};   // bit0 = node 0; [BMW]=0
static __device__ unsigned g_bm2[BMW + 1] = {1u};
static __device__ int      g_s1[S1CAP];             // s1[0]=0 (node 0)
static __device__ int      g_e0[E0CAP];
static __device__ int      g_s2[ECAP];              // s2[0]=0
static __device__ int2     g_e1[ECAP];
static __device__ int      g_cnt1 = 1, g_cnt2 = 1, g_cntE0 = 0, g_cntE1 = 0;
static __device__ float    g_hlin[ECAP][H];
static __device__ float    g_acc1[S1CAP][H];        // zero-init; tail re-zeros
static __device__ float    g_h2[S1CAP][H];

// ---------------------------------------------------------------------------
__device__ __forceinline__ void s1_one(const int* __restrict__ src, int d, int idx) {
    if (d == 0) {
        int s = __ldcg(&src[idx]);
        int p = atomicAdd(&g_cntE0, 1);
        if (p < E0CAP) g_e0[p] = s;
        if (atomicCAS(&g_flag1[s], 0, -1) == 0) {
            int q = atomicAdd(&g_cnt1, 1);
            if (q < S1CAP) g_s1[q] = s;
            g_flag1[s] = q + 1;
            atomicOr(&g_bm1[s >> 5], 1u << (s & 31));
            if (atomicCAS(&g_flag2[s], 0, -1) == 0) {
                int r = atomicAdd(&g_cnt2, 1);
                if (r < ECAP) g_s2[r] = s;
                g_flag2[s] = r + 1;
                atomicOr(&g_bm2[s >> 5], 1u << (s & 31));
            }
        }
    }
}

__device__ __forceinline__ void s2_one(const unsigned* sbm,
                                       const int* __restrict__ src, int d, int idx) {
    if ((sbm[(unsigned)d >> 5] >> (d & 31)) & 1u) {
        int s = __ldcg(&src[idx]);
        int p = atomicAdd(&g_cntE1, 1);
        if (p < ECAP) g_e1[p] = make_int2(s, d);
        if (atomicCAS(&g_flag2[s], 0, -1) == 0) {
            int r = atomicAdd(&g_cnt2, 1);
            if (r < ECAP) g_s2[r] = s;
            g_flag2[s] = r + 1;
            atomicOr(&g_bm2[s >> 5], 1u << (s & 31));
        }
    }
}

// ---------------------------------------------------------------------------
// scan1: dst==0. umin over 16 edges, one test, rare slow path.
__global__ void __launch_bounds__(SCAN_T, 4)
k_scan1(const int* __restrict__ src, const int* __restrict__ dst, int E) {
    int gid = blockIdx.x * SCAN_T + threadIdx.x;
    int E4 = E >> 2;
    const int4* d4 = (const int4*)dst;
    int i0 = gid, i1 = gid + NTH, i2 = gid + 2 * NTH, i3 = gid + 3 * NTH;
    const int4 sv = make_int4(SENT, SENT, SENT, SENT);
    int4 v0 = (i0 < E4) ? __ldcg(&d4[i0]) : sv;
    int4 v1 = (i1 < E4) ? __ldcg(&d4[i1]) : sv;
    int4 v2 = (i2 < E4) ? __ldcg(&d4[i2]) : sv;
    int4 v3 = (i3 < E4) ? __ldcg(&d4[i3]) : sv;
    unsigned m0 = umin(umin((unsigned)v0.x, (unsigned)v0.y), umin((unsigned)v0.z, (unsigned)v0.w));
    unsigned m1 = umin(umin((unsigned)v1.x, (unsigned)v1.y), umin((unsigned)v1.z, (unsigned)v1.w));
    unsigned m2 = umin(umin((unsigned)v2.x, (unsigned)v2.y), umin((unsigned)v2.z, (unsigned)v2.w));
    unsigned m3 = umin(umin((unsigned)v3.x, (unsigned)v3.y), umin((unsigned)v3.z, (unsigned)v3.w));
    if (umin(umin(m0, m1), umin(m2, m3)) == 0u) {
        s1_one(src, v0.x, 4*i0); s1_one(src, v0.y, 4*i0+1); s1_one(src, v0.z, 4*i0+2); s1_one(src, v0.w, 4*i0+3);
        s1_one(src, v1.x, 4*i1); s1_one(src, v1.y, 4*i1+1); s1_one(src, v1.z, 4*i1+2); s1_one(src, v1.w, 4*i1+3);
        s1_one(src, v2.x, 4*i2); s1_one(src, v2.y, 4*i2+1); s1_one(src, v2.z, 4*i2+2); s1_one(src, v2.w, 4*i2+3);
        s1_one(src, v3.x, 4*i3); s1_one(src, v3.y, 4*i3+1); s1_one(src, v3.z, 4*i3+2); s1_one(src, v3.w, 4*i3+3);
    }
    // generic tail (covers E4 > 4*NTH and E % 4 != 0; no-op for this shape)
    for (int i = gid + 4 * NTH; i < E4; i += NTH) {
        int4 v = __ldcg(&d4[i]);
        s1_one(src, v.x, 4*i); s1_one(src, v.y, 4*i+1); s1_one(src, v.z, 4*i+2); s1_one(src, v.w, 4*i+3);
    }
    for (int j = (E4 << 2) + gid; j < E; j += NTH) s1_one(src, __ldcg(&dst[j]), j);
}

// ---------------------------------------------------------------------------
// scan2: dst in bm1. 16 funnel probes OR-combined into one bit test.
__global__ void __launch_bounds__(SCAN_T, 4)
k_scan2(const int* __restrict__ src, const int* __restrict__ dst, int E) {
    __shared__ unsigned sbm[BMW + 1];
    for (int k = threadIdx.x; k < BMW + 1; k += SCAN_T) sbm[k] = __ldcg(&g_bm1[k]);
    __syncthreads();
    int gid = blockIdx.x * SCAN_T + threadIdx.x;
    int E4 = E >> 2;
    const int4* d4 = (const int4*)dst;
    int i0 = gid, i1 = gid + NTH, i2 = gid + 2 * NTH, i3 = gid + 3 * NTH;
    const int4 sv = make_int4(SENT, SENT, SENT, SENT);
    int4 v0 = (i0 < E4) ? __ldcg(&d4[i0]) : sv;
    int4 v1 = (i1 < E4) ? __ldcg(&d4[i1]) : sv;
    int4 v2 = (i2 < E4) ? __ldcg(&d4[i2]) : sv;
    int4 v3 = (i3 < E4) ? __ldcg(&d4[i3]) : sv;
    #define PRB(d) __funnelshift_r(sbm[(unsigned)(d) >> 5], 0u, (d))
    unsigned acc = PRB(v0.x) | PRB(v0.y) | PRB(v0.z) | PRB(v0.w)
                 | PRB(v1.x) | PRB(v1.y) | PRB(v1.z) | PRB(v1.w)
                 | PRB(v2.x) | PRB(v2.y) | PRB(v2.z) | PRB(v2.w)
                 | PRB(v3.x) | PRB(v3.y) | PRB(v3.z) | PRB(v3.w);
    if (acc & 1u) {
        s2_one(sbm, src, v0.x, 4*i0); s2_one(sbm, src, v0.y, 4*i0+1); s2_one(sbm, src, v0.z, 4*i0+2); s2_one(sbm, src, v0.w, 4*i0+3);
        s2_one(sbm, src, v1.x, 4*i1); s2_one(sbm, src, v1.y, 4*i1+1); s2_one(sbm, src, v1.z, 4*i1+2); s2_one(sbm, src, v1.w, 4*i1+3);
        s2_one(sbm, src, v2.x, 4*i2); s2_one(sbm, src, v2.y, 4*i2+1); s2_one(sbm, src, v2.z, 4*i2+2); s2_one(sbm, src, v2.w, 4*i2+3);
        s2_one(sbm, src, v3.x, 4*i3); s2_one(sbm, src, v3.y, 4*i3+1); s2_one(sbm, src, v3.z, 4*i3+2); s2_one(sbm, src, v3.w, 4*i3+3);
    }
    for (int i = gid + 4 * NTH; i < E4; i += NTH) {
        int4 v = __ldcg(&d4[i]);
        s2_one(sbm, src, v.x, 4*i); s2_one(sbm, src, v.y, 4*i+1); s2_one(sbm, src, v.z, 4*i+2); s2_one(sbm, src, v.w, 4*i+3);
    }
    for (int j = (E4 << 2) + gid; j < E; j += NTH) {
        int d = __ldcg(&dst[j]);
        s2_one(sbm, src, d, j);
    }
    #undef PRB
}

// ---------------------------------------------------------------------------
// scan3: dst in bm2 -> deg atomics. Same probe structure.
__global__ void __launch_bounds__(SCAN_T, 4)
k_scan3(const int* __restrict__ dst, int E) {
    __shared__ unsigned sbm[BMW + 1];
    for (int k = threadIdx.x; k < BMW + 1; k += SCAN_T) sbm[k] = __ldcg(&g_bm2[k]);
    __syncthreads();
    int gid = blockIdx.x * SCAN_T + threadIdx.x;
    int E4 = E >> 2;
    const int4* d4 = (const int4*)dst;
    int i0 = gid, i1 = gid + NTH, i2 = gid + 2 * NTH, i3 = gid + 3 * NTH;
    const int4 sv = make_int4(SENT, SENT, SENT, SENT);
    int4 v0 = (i0 < E4) ? __ldcg(&d4[i0]) : sv;
    int4 v1 = (i1 < E4) ? __ldcg(&d4[i1]) : sv;
    int4 v2 = (i2 < E4) ? __ldcg(&d4[i2]) : sv;
    int4 v3 = (i3 < E4) ? __ldcg(&d4[i3]) : sv;
    #define PRB(d) __funnelshift_r(sbm[(unsigned)(d) >> 5], 0u, (d))
    #define S3(d)  if ((sbm[(unsigned)(d) >> 5] >> ((d) & 31)) & 1u) atomicAdd(&g_deg[d], 1)
    unsigned acc = PRB(v0.x) | PRB(v0.y) | PRB(v0.z) | PRB(v0.w)
                 | PRB(v1.x) | PRB(v1.y) | PRB(v1.z) | PRB(v1.w)
                 | PRB(v2.x) | PRB(v2.y) | PRB(v2.z) | PRB(v2.w)
                 | PRB(v3.x) | PRB(v3.y) | PRB(v3.z) | PRB(v3.w);
    if (acc & 1u) {
        S3(v0.x); S3(v0.y); S3(v0.z); S3(v0.w);
        S3(v1.x); S3(v1.y); S3(v1.z); S3(v1.w);
        S3(v2.x); S3(v2.y); S3(v2.z); S3(v2.w);
        S3(v3.x); S3(v3.y); S3(v3.z); S3(v3.w);
    }
    for (int i = gid + 4 * NTH; i < E4; i += NTH) {
        int4 v = __ldcg(&d4[i]);
        S3(v.x); S3(v.y); S3(v.z); S3(v.w);
    }
    for (int j = (E4 << 2) + gid; j < E; j += NTH) { int d = __ldcg(&dst[j]); S3(d); }
    #undef S3
    #undef PRB
}

// ---------------------------------------------------------------------------
// hlin = x[:,u] @ W1 for u in S2. 16 nodes staged per block.
__global__ void __launch_bounds__(HLIN_T)
k_hlin(const float* __restrict__ x, const float* __restrict__ W1, int N) {
    __shared__ float sW1[IND * H];    // 32 KB
    __shared__ float sx[HN][IND];     // 8 KB
    int tid = threadIdx.x;
    for (int k = tid; k < IND * H; k += HLIN_T) sW1[k] = W1[k];
    int m2 = g_cnt2; if (m2 > ECAP) m2 = ECAP;
    for (int base = blockIdx.x * HN; base < m2; base += HLIN_B * HN) {
        for (int k = tid; k < HN * IND; k += HLIN_T) {
            int node = k >> 7;
            int d    = k & 127;
            int j    = base + node;
            if (j < m2) sx[node][d] = __ldg(&x[(size_t)d * N + g_s2[j]]);
        }
        __syncthreads();
        for (int k = tid; k < HN * H; k += HLIN_T) {
            int node = k >> 6;
            int o    = k & 63;
            int j    = base + node;
            if (j < m2) {
                float acc = 0.0f;
                #pragma unroll
                for (int d = 0; d < IND; d++) acc += sx[node][d] * sW1[d * H + o];
                g_hlin[j][o] = acc;
            }
        }
        __syncthreads();
    }
}

// ---------------------------------------------------------------------------
// Layer-1 aggregation: self loops + edges in one index space; one dependent
// chain per group, metadata via __ldg issued concurrently.
__global__ void __launch_bounds__(256)
k_agg(void) {
    int tt      = threadIdx.x & 63;
    int group   = blockIdx.x * 4 + (threadIdx.x >> 6);
    int ngroups = gridDim.x * 4;
    int m1 = g_cnt1; if (m1 > S1CAP) m1 = S1CAP;
    int mE = g_cntE1; if (mE > ECAP) mE = ECAP;
    int total = m1 + mE;
    for (int t = group; t < total; t += ngroups) {
        if (t < m1) {
            int u  = __ldg(&g_s1[t]);
            float di = rsqrtf((float)__ldg(&g_deg[u]) + 1.0f);
            int p2 = __ldg(&g_flag2[u]) - 1;
            atomicAdd(&g_acc1[t][tt], di * di * __ldg(&g_hlin[p2][tt]));
        } else {
            int e = t - m1;
            int2 ed = __ldg(&g_e1[e]);
            int dp = __ldg(&g_flag1[ed.y]) - 1;
            int sp = __ldg(&g_flag2[ed.x]) - 1;
            float nrm = rsqrtf((float)__ldg(&g_deg[ed.x]) + 1.0f)
                      * rsqrtf((float)__ldg(&g_deg[ed.y]) + 1.0f);
            atomicAdd(&g_acc1[dp][tt], nrm * __ldg(&g_hlin[sp][tt]));
        }
    }
}

// ---------------------------------------------------------------------------
// Tail: h2 for S1 nodes, node-0 layer-2 agg, LSTM, FC -> out.
// EPILOGUE: restore canonical state (flags, bitmaps, deg, acc1, counters)
// so the next graph replay starts from the identical seeded state.
__global__ void __launch_bounds__(512)
k_tail(const float* __restrict__ b1, const float* __restrict__ W2,
       const float* __restrict__ b2, const float* __restrict__ w_ih,
       const float* __restrict__ b_ih, const float* __restrict__ b_hh,
       const float* __restrict__ fc_w, const float* __restrict__ fc_b,
       float* __restrict__ out) {
    __shared__ float sW2[H * H];        // 16 KB
    __shared__ float h1buf[8][H];       // 2 KB
    __shared__ float z[H], gates[4 * H], red[H];
    __shared__ float scof[256];
    __shared__ int   sspb[256];

    int tid = threadIdx.x;
    for (int k = tid; k < H * H; k += 512) sW2[k] = W2[k];
    __syncthreads();

    int m1 = g_cnt1; if (m1 > S1CAP) m1 = S1CAP;
    int m2 = g_cnt2; if (m2 > ECAP)  m2 = ECAP;
    int sub = tid >> 6, tt = tid & 63;
    for (int j0 = 0; j0 < m1; j0 += 8) {
        int j = j0 + sub;
        if (j < m1) h1buf[sub][tt] = fmaxf(g_acc1[j][tt] + b1[tt], 0.0f);
        __syncthreads();
        if (j < m1) {
            float acc = 0.0f;
            #pragma unroll
            for (int h = 0; h < H; h++) acc += h1buf[sub][h] * sW2[h * H + tt];
            g_h2[j][tt] = acc;
        }
        __syncthreads();
    }

    // node-0 layer-2 aggregation
    int m0 = g_cntE0; if (m0 > E0CAP) m0 = E0CAP;
    float d0 = rsqrtf((float)g_deg[0] + 1.0f);
    float zv = 0.0f;
    if (tid < H) zv = b2[tid] + d0 * d0 * g_h2[0][tid];
    for (int base = 0; base < m0; base += 256) {
        int k = base + tid;
        if (tid < 256 && k < m0) {
            int s = g_e0[k];
            scof[tid] = rsqrtf((float)g_deg[s] + 1.0f) * d0;
            sspb[tid] = g_flag1[s] - 1;
        }
        __syncthreads();
        int lim = m0 - base; if (lim > 256) lim = 256;
        if (tid < H)
            for (int e = 0; e < lim; e++) zv += scof[e] * g_h2[sspb[e]][tid];
        __syncthreads();
    }
    if (tid < H) z[tid] = zv;
    __syncthreads();

    if (tid < 4 * H) {
        float a = b_ih[tid] + b_hh[tid];
        #pragma unroll
        for (int h = 0; h < H; h++) a += __ldg(&w_ih[tid * H + h]) * z[h];
        gates[tid] = a;
    }
    __syncthreads();
    if (tid < H) {
        float ig = gates[tid];
        float gg = gates[2 * H + tid];
        float og = gates[3 * H + tid];
        float si = 1.0f / (1.0f + expf(-ig));
        float c  = si * tanhf(gg);
        float so = 1.0f / (1.0f + expf(-og));
        float hy = so * tanhf(c);
        red[tid] = hy * fc_w[tid];
    }
    __syncthreads();
    if (tid == 0) {
        float s = 0.0f;
        for (int k = 0; k < H; k++) s += red[k];
        out[0] = s + fc_b[0];
    }

    // ---------------- epilogue: reset to canonical state ----------------
    __syncthreads();   // all reads of g_* above are complete
    for (int j = 1 + tid; j < m1; j += 512) {
        int u = g_s1[j];
        g_flag1[u] = 0;
        atomicAnd(&g_bm1[u >> 5], ~(1u << (u & 31)));
    }
    for (int j = 1 + tid; j < m2; j += 512) {
        int u = g_s2[j];
        g_flag2[u] = 0;
        g_deg[u]   = 0;
        atomicAnd(&g_bm2[u >> 5], ~(1u << (u & 31)));
    }
    for (int k = tid; k < m1 * H; k += 512) ((float*)g_acc1)[k] = 0.0f;
    __syncthreads();
    if (tid == 0) {
        g_cnt1 = 1; g_cnt2 = 1; g_cntE0 = 0; g_cntE1 = 0;
        g_s1[0] = 0; g_s2[0] = 0;
        g_flag1[0] = 1; g_flag2[0] = 1;
        g_deg[0] = 0;
        atomicOr(&g_bm1[0], 1u);
        atomicOr(&g_bm2[0], 1u);
    }
}

// ---------------------------------------------------------------------------
extern "C" void kernel_launch(void* const* d_in, const int* in_sizes, int n_in,
                              void* d_out, int out_size) {
    const float* x    = (const float*)d_in[0];
    const int*   ei   = (const int*)d_in[1];
    const float* W1   = (const float*)d_in[2];
    const float* b1   = (const float*)d_in[3];
    const float* W2   = (const float*)d_in[4];
    const float* b2   = (const float*)d_in[5];
    const float* w_ih = (const float*)d_in[6];
    // d_in[7] = w_hh (unused: h0 = c0 = 0)
    const float* b_ih = (const float*)d_in[8];
    const float* b_hh = (const float*)d_in[9];
    const float* fc_w = (const float*)d_in[10];
    const float* fc_b = (const float*)d_in[11];
    float* out = (float*)d_out;

    int N = in_sizes[0] / IND;
    int E = in_sizes[1] / 2;
    const int* src = ei;
    const int* dst = ei + E;

    k_scan1<<<SCAN_B, SCAN_T>>>(src, dst, E);
    k_scan2<<<SCAN_B, SCAN_T>>>(src, dst, E);
    k_scan3<<<SCAN_B, SCAN_T>>>(dst, E);
    k_hlin<<<HLIN_B, HLIN_T>>>(x, W1, N);
    k_agg<<<296, 256>>>();
    k_tail<<<1, 512>>>(b1, W2, b2, w_ih, b_ih, b_hh, fc_w, fc_b, out);
}